// round 14
// baseline (speedup 1.0000x reference)
#include <cuda_runtime.h>
#include <math.h>
#include <stdint.h>

#define BATCH 4
#define SEQ   4096
#define NROWS (BATCH * SEQ)
#define EMB   768
#define QD    64
#define CCOLS 192

// ---------------- scratch ----------------------------------------------------
__device__ float g_C[(size_t)NROWS * CCOLS];
__device__ __align__(16) int8_t g_Bh[(size_t)CCOLS * EMB];  // n-major: [n][k]
__device__ __align__(16) int8_t g_Bl[(size_t)CCOLS * EMB];
__device__ float g_Spart[128 * 64];
__device__ float g_S[BATCH * QD];

// ---------------- PTX helpers ------------------------------------------------
__device__ __forceinline__ uint32_t smem_u32(const void* p) {
    uint32_t a;
    asm("{ .reg .u64 t; cvta.to.shared.u64 t, %1; cvt.u32.u64 %0, t; }"
        : "=r"(a) : "l"(p));
    return a;
}
#define LDM4(r, addr)                                                        \
    asm volatile("ldmatrix.sync.aligned.m8n8.x4.shared.b16 {%0,%1,%2,%3}, [%4];" \
                 : "=r"((r)[0]), "=r"((r)[1]), "=r"((r)[2]), "=r"((r)[3])    \
                 : "r"(addr))
#define IMMA(d, a0, a1, b0, b1)                                              \
    asm volatile(                                                            \
        "mma.sync.aligned.m16n8k32.row.col.s32.s8.s8.s32 "                   \
        "{%0,%1,%2,%3}, {%4,%5,%6,%7}, {%8,%9}, {%0,%1,%2,%3};"              \
        : "+r"((d)[0]), "+r"((d)[1]), "+r"((d)[2]), "+r"((d)[3])             \
        : "r"((a0)[0]), "r"((a0)[1]), "r"((a1)[0]), "r"((a1)[1]),            \
          "r"(b0), "r"(b1))
#define CP16(dst, src)                                                       \
    asm volatile("cp.async.cg.shared.global [%0], [%1], 16;"                 \
                 :: "r"(dst), "l"(src))
#define CP_COMMIT() asm volatile("cp.async.commit_group;")
#define CP_WAIT1()  asm volatile("cp.async.wait_group 1;")
#define CP_WAIT0()  asm volatile("cp.async.wait_group 0;")

// 15-bit two-limb int8 quantization: v ~= (h*128 + l) * s, h,l in [-127,127]
__device__ __forceinline__ void quant4(float4 v, float inv_s,
                                       uint32_t& uh, uint32_t& ul) {
    float f[4] = {v.x, v.y, v.z, v.w};
    uint32_t h_ = 0, l_ = 0;
#pragma unroll
    for (int j = 0; j < 4; j++) {
        float af = rintf(fminf(fmaxf(f[j] * inv_s, -16256.f), 16256.f));
        int h = (int)rintf(af * 0.0078125f);
        int l = (int)af - (h << 7);
        h_ |= (uint32_t)(h & 0xff) << (8 * j);
        l_ |= (uint32_t)(l & 0xff) << (8 * j);
    }
    uh = h_; ul = l_;
}

#define INV_SX 2709.3333f            /* 16256/6   : |x| < 6   */
#define INV_SW 65024.0f              /* 16256/0.25: |W| < 0.25 */
#define OUT_SCALE (1.5f / (16256.f * 16256.f))   /* s_x * s_w */

// ---------------- weight transpose+split: g_B[n][k] int8 limbs ----------------
// 36 blocks: kt = b%12 (k-tile of 64), nt = b/12 (Wq/Wk/Wv). Smem transpose.
__global__ __launch_bounds__(256) void prep_w(
    const float* __restrict__ Wq, const float* __restrict__ Wk,
    const float* __restrict__ Wv)
{
    __shared__ float s[64][65];
    const int b = blockIdx.x;
    const int kt = b % 12, nt = b / 12;
    const float* W = (nt == 0) ? Wq : (nt == 1) ? Wk : Wv;

#pragma unroll
    for (int i = 0; i < 16; i++) {
        int idx = threadIdx.x + 256 * i;     // 4096 = 64k x 64n
        int r = idx >> 6, c = idx & 63;
        s[r][c] = W[(size_t)(kt * 64 + r) * 64 + c];
    }
    __syncthreads();

#pragma unroll
    for (int i = 0; i < 4; i++) {
        int idx = threadIdx.x + 256 * i;     // 1024 = 64n x 16 k-quads
        int n = idx >> 4, kq = idx & 15;
        float4 v = make_float4(s[kq * 4][n], s[kq * 4 + 1][n],
                               s[kq * 4 + 2][n], s[kq * 4 + 3][n]);
        uint32_t uh, ul;
        quant4(v, INV_SW, uh, ul);
        size_t o = (size_t)(nt * 64 + n) * EMB + kt * 64 + kq * 4;
        *(uint32_t*)(g_Bh + o) = uh;
        *(uint32_t*)(g_Bl + o) = ul;
    }
}

// ---------------- pipelined int8 two-limb IMMA GEMM ---------------------------
// BM=128, BN=192, BK=64, k32 per mma (2 ksteps/chunk). Strides 80B.
#define SA_BYTES 10240               /* 128 rows x 80 */
#define SB_BYTES 15360               /* 192 rows x 80 */
#define SA_OFF(s, h) (((s) * 2 + (h)) * SA_BYTES)
#define SB_OFF(s, h) (40960 + ((s) * 2 + (h)) * SB_BYTES)
#define SM_TOTAL 102400

__global__ __launch_bounds__(256, 1)
void mma_gemm(const float* __restrict__ x,
              const float* __restrict__ bq, const float* __restrict__ bk,
              const float* __restrict__ bv)
{
    extern __shared__ char smem[];
    __shared__ float sbias[CCOLS];
    __shared__ float smemV[4][64];

    const uint32_t sb = smem_u32(smem);
    const int tid = threadIdx.x;
    const int wid = tid >> 5, lane = tid & 31;
    const int wm = wid & 3, wn = wid >> 2;
    const int rowTile = blockIdx.x * 128;

    if (tid < CCOLS)
        sbias[tid] = (tid < 64) ? bq[tid] : (tid < 128) ? bk[tid - 64]
                                                        : bv[tid - 128];

    int acc_hh[2][12][4], acc_x[2][12][4];
#pragma unroll
    for (int i = 0; i < 2; i++)
#pragma unroll
        for (int j = 0; j < 12; j++)
#pragma unroll
            for (int l = 0; l < 4; l++) { acc_hh[i][j][l] = 0; acc_x[i][j][l] = 0; }

    const int g = lane >> 3, r = lane & 7;
    const int a_off = (r + ((g & 1) ? 8 : 0)) * 80 + ((g >= 2) ? 16 : 0);
    const int b_off = (r + ((g >= 2) ? 8 : 0)) * 80 + ((g & 1) ? 16 : 0);

    uint32_t aAh[2], aAl[2], aBh[2], aBl[2];
#pragma unroll
    for (int s = 0; s < 2; s++) {
        aAh[s] = sb + SA_OFF(s, 0) + wm * 32 * 80 + a_off;
        aAl[s] = sb + SA_OFF(s, 1) + wm * 32 * 80 + a_off;
        aBh[s] = sb + SB_OFF(s, 0) + wn * 96 * 80 + b_off;
        aBl[s] = sb + SB_OFF(s, 1) + wn * 96 * 80 + b_off;
    }

    // packed int8 A, one chunk ahead (hi/lo limbs, 4 k per uint32)
    uint32_t Ah8[8], Al8[8];

#define LDG_A_CONV(ch)                                                       \
    do {                                                                     \
        const int k0_ = (ch) * 64;                                           \
        _Pragma("unroll")                                                    \
        for (int i = 0; i < 8; i++) {                                        \
            int idx = tid + i * 256;                                         \
            int rr = idx >> 4, c4 = idx & 15;                                \
            float4 v = *(const float4*)(x + (size_t)(rowTile + rr) * EMB +   \
                                        k0_ + c4 * 4);                       \
            quant4(v, INV_SX, Ah8[i], Al8[i]);                               \
        }                                                                    \
    } while (0)

#define STS_A(ch)                                                            \
    do {                                                                     \
        const int s_ = (ch) & 1;                                             \
        _Pragma("unroll")                                                    \
        for (int i = 0; i < 8; i++) {                                        \
            int idx = tid + i * 256;                                         \
            int rr = idx >> 4, c4 = idx & 15;                                \
            *(uint32_t*)(smem + SA_OFF(s_, 0) + rr * 80 + c4 * 4) = Ah8[i];  \
            *(uint32_t*)(smem + SA_OFF(s_, 1) + rr * 80 + c4 * 4) = Al8[i];  \
        }                                                                    \
    } while (0)

#define LDG_B(ch)                                                            \
    do {                                                                     \
        const int s_ = (ch) & 1;                                             \
        const int k0_ = (ch) * 64;                                           \
        _Pragma("unroll")                                                    \
        for (int i = 0; i < 3; i++) {                                        \
            int j = tid + i * 256;            /* 0..767: 192n x 4 quads */   \
            int row = j >> 2, c = j & 3;                                     \
            CP16(sb + SB_OFF(s_, 0) + row * 80 + c * 16,                     \
                 g_Bh + (size_t)row * EMB + k0_ + c * 16);                   \
            CP16(sb + SB_OFF(s_, 1) + row * 80 + c * 16,                     \
                 g_Bl + (size_t)row * EMB + k0_ + c * 16);                   \
        }                                                                    \
    } while (0)

    // ---- prologue ----
    LDG_B(0); CP_COMMIT();
    LDG_A_CONV(0);
    STS_A(0);
    LDG_B(1); CP_COMMIT();
    LDG_A_CONV(1);

    // ---- main loop ----
    for (int ch = 0; ch < 12; ch++) {
        const int s = ch & 1;
        if (ch < 11) CP_WAIT1(); else CP_WAIT0();
        __syncthreads();

#pragma unroll
        for (int ks = 0; ks < 2; ks++) {
            uint32_t ah[2][4], al[2][4];
            LDM4(ah[0], aAh[s] + ks * 32);
            LDM4(ah[1], aAh[s] + 1280 + ks * 32);
            LDM4(al[0], aAl[s] + ks * 32);
            LDM4(al[1], aAl[s] + 1280 + ks * 32);
#pragma unroll
            for (int nt = 0; nt < 6; nt++) {
                uint32_t bh[4], bl[4];
                LDM4(bh, aBh[s] + nt * 1280 + ks * 32);
                LDM4(bl, aBl[s] + nt * 1280 + ks * 32);
#pragma unroll
                for (int sub = 0; sub < 2; sub++) {
                    const int j = nt * 2 + sub;
#pragma unroll
                    for (int mt = 0; mt < 2; mt++) {
                        IMMA(acc_hh[mt][j], &ah[mt][0], &ah[mt][2],
                             bh[2 * sub], bh[2 * sub + 1]);
                        IMMA(acc_x[mt][j], &ah[mt][0], &ah[mt][2],
                             bl[2 * sub], bl[2 * sub + 1]);
                        IMMA(acc_x[mt][j], &al[mt][0], &al[mt][2],
                             bh[2 * sub], bh[2 * sub + 1]);
                    }
                }
            }
            if (ks == 0 && ch < 11)
                STS_A(ch + 1);        // A[s^1] only — safe behind top barrier
        }
        if (ch < 10) {
            __syncthreads();          // all reads of B[s] complete
            LDG_B(ch + 2); CP_COMMIT();
            LDG_A_CONV(ch + 2);
        }
    }

    // ---- epilogue: combine limbs + bias -> g_C ----
    const int rbase = rowTile + wm * 32 + (lane >> 2);
#pragma unroll
    for (int mt = 0; mt < 2; mt++)
#pragma unroll
        for (int j = 0; j < 12; j++) {
            int col = wn * 96 + j * 8 + 2 * (lane & 3);
            float b0 = sbias[col], b1 = sbias[col + 1];
            int row = rbase + mt * 16;
            float c0 = ((float)acc_hh[mt][j][0] * 16384.f +
                        (float)acc_x[mt][j][0] * 128.f) * OUT_SCALE + b0;
            float c1 = ((float)acc_hh[mt][j][1] * 16384.f +
                        (float)acc_x[mt][j][1] * 128.f) * OUT_SCALE + b1;
            float c2 = ((float)acc_hh[mt][j][2] * 16384.f +
                        (float)acc_x[mt][j][2] * 128.f) * OUT_SCALE + b0;
            float c3 = ((float)acc_hh[mt][j][3] * 16384.f +
                        (float)acc_x[mt][j][3] * 128.f) * OUT_SCALE + b1;
            *(float2*)&g_C[(size_t)row * CCOLS + col] = make_float2(c0, c1);
            *(float2*)&g_C[(size_t)(row + 8) * CCOLS + col] = make_float2(c2, c3);
        }

    // ---- per-CTA V column sums (cols 128..191 live in wn==1, j>=4) ----
    if (wn == 1) {
#pragma unroll
        for (int j = 4; j < 12; j++) {
            int hh0 = acc_hh[0][j][0] + acc_hh[0][j][2] + acc_hh[1][j][0] + acc_hh[1][j][2];
            int xx0 = acc_x[0][j][0] + acc_x[0][j][2] + acc_x[1][j][0] + acc_x[1][j][2];
            int hh1 = acc_hh[0][j][1] + acc_hh[0][j][3] + acc_hh[1][j][1] + acc_hh[1][j][3];
            int xx1 = acc_x[0][j][1] + acc_x[0][j][3] + acc_x[1][j][1] + acc_x[1][j][3];
            float s0 = ((float)hh0 * 16384.f + (float)xx0 * 128.f) * OUT_SCALE;
            float s1 = ((float)hh1 * 16384.f + (float)xx1 * 128.f) * OUT_SCALE;
#pragma unroll
            for (int m = 4; m <= 16; m <<= 1) {
                s0 += __shfl_xor_sync(0xffffffffu, s0, m);
                s1 += __shfl_xor_sync(0xffffffffu, s1, m);
            }
            if (lane < 4) {
                int d = (j - 4) * 8 + 2 * lane;
                smemV[wm][d] = s0;
                smemV[wm][d + 1] = s1;
            }
        }
    }
    __syncthreads();
    if (tid < 64)
        g_Spart[blockIdx.x * 64 + tid] =
            smemV[0][tid] + smemV[1][tid] + smemV[2][tid] + smemV[3][tid] +
            128.f * sbias[128 + tid];
}

// ---------------- parallel final V-sum: 4 blocks, two-stage --------------------
__global__ __launch_bounds__(256) void sum_v_final()
{
    __shared__ float sm[4][64];
    const int b = blockIdx.x;
    const int d = threadIdx.x & 63;
    const int grp = threadIdx.x >> 6;
    float s = 0.f;
#pragma unroll
    for (int c = 0; c < 8; c++)
        s += g_Spart[(b * 32 + grp * 8 + c) * 64 + d];
    sm[grp][d] = s;
    __syncthreads();
    if (grp == 0) {
        float t = sm[0][d] + sm[1][d] + sm[2][d] + sm[3][d];
#pragma unroll
        for (int j = 0; j < 3; j++)
            t -= g_C[(size_t)(b * SEQ + j) * CCOLS + 128 + d];
        g_S[b * 64 + d] = t;
    }
}

// ---------------- epilogue: one warp per row, reads g_S directly ---------------
__global__ __launch_bounds__(256) void attn_epilogue(float* __restrict__ out)
{
    const int lane = threadIdx.x;
    const int row = blockIdx.x * 8 + threadIdx.y;
    const int loc = row & (SEQ - 1);
    const int b = row >> 12;

    const float* Crow = g_C + (size_t)row * CCOLS;
    float2 q = *(const float2*)(Crow + lane * 2);
    const float* Kc = Crow + 64;

    float2 k1 = *(const float2*)(Kc + lane * 2);
    float d1 = q.x * k1.x + q.y * k1.y;
    float d0 = 0.f, d2 = 0.f;
    if (loc > 0) {
        float2 k0 = *(const float2*)(Kc - CCOLS + lane * 2);
        d0 = q.x * k0.x + q.y * k0.y;
    }
    if (loc < SEQ - 1) {
        float2 k2 = *(const float2*)(Kc + CCOLS + lane * 2);
        d2 = q.x * k2.x + q.y * k2.y;
    }
#pragma unroll
    for (int off = 16; off; off >>= 1) {
        d0 += __shfl_xor_sync(0xffffffffu, d0, off);
        d1 += __shfl_xor_sync(0xffffffffu, d1, off);
        d2 += __shfl_xor_sync(0xffffffffu, d2, off);
    }
    float e0 = (loc > 0) ? __expf(d0) : 1.f;
    float e1 = __expf(d1);
    float e2 = (loc < SEQ - 1) ? __expf(d2) : 1.f;
    float rZ = __fdividef(1.f, e0 + e1 + e2 + (float)(SEQ - 3));

    const float* Vb = g_C + (size_t)(b * SEQ) * CCOLS + 128;
    float2 v0 = *(const float2*)(Vb + lane * 2);
    float2 v1 = *(const float2*)(Vb + CCOLS + lane * 2);
    float2 v2 = *(const float2*)(Vb + 2 * CCOLS + lane * 2);
    float2 s = *(const float2*)(g_S + b * 64 + lane * 2);

    float2 o;
    o.x = (e0 * v0.x + e1 * v1.x + e2 * v2.x + s.x) * rZ;
    o.y = (e0 * v0.y + e1 * v1.y + e2 * v2.y + s.y) * rZ;
    *(float2*)(out + (size_t)row * QD + lane * 2) = o;
}

// ---------------- launch -------------------------------------------------------
extern "C" void kernel_launch(void* const* d_in, const int* in_sizes, int n_in,
                              void* d_out, int out_size)
{
    const float* x  = (const float*)d_in[0];
    const float* Wq = (const float*)d_in[1];
    const float* bq = (const float*)d_in[2];
    const float* Wk = (const float*)d_in[3];
    const float* bk = (const float*)d_in[4];
    const float* Wv = (const float*)d_in[5];
    const float* bv = (const float*)d_in[6];
    float* out = (float*)d_out;

    cudaFuncSetAttribute(mma_gemm, cudaFuncAttributeMaxDynamicSharedMemorySize,
                         SM_TOTAL);

    prep_w<<<36, 256>>>(Wq, Wk, Wv);
    mma_gemm<<<NROWS / 128, 256, SM_TOTAL>>>(x, bq, bk, bv);
    sum_v_final<<<BATCH, 256>>>();
    attn_epilogue<<<NROWS / 8, dim3(32, 8)>>>(out);
}

// round 15
// speedup vs baseline: 2.4314x; 2.4314x over previous
#include <cuda_runtime.h>
#include <cuda_bf16.h>
#include <math.h>
#include <stdint.h>

#define BATCH 4
#define SEQ   4096
#define NROWS (BATCH * SEQ)
#define EMB   768
#define QD    64
#define CCOLS 192

// ---------------- scratch ----------------------------------------------------
__device__ float g_C[(size_t)NROWS * CCOLS];
__device__ __nv_bfloat16 g_Bh[(size_t)EMB * CCOLS];  // k-major: [k][n]
__device__ __nv_bfloat16 g_Bl[(size_t)EMB * CCOLS];
__device__ float g_Spart[128 * 64];                  // per-CTA V col sums
__device__ float g_S[BATCH * QD];

// ---------------- PTX helpers ------------------------------------------------
__device__ __forceinline__ uint32_t smem_u32(const void* p) {
    uint32_t a;
    asm("{ .reg .u64 t; cvta.to.shared.u64 t, %1; cvt.u32.u64 %0, t; }"
        : "=r"(a) : "l"(p));
    return a;
}
#define LDM4(r, addr)                                                        \
    asm volatile("ldmatrix.sync.aligned.m8n8.x4.shared.b16 {%0,%1,%2,%3}, [%4];" \
                 : "=r"((r)[0]), "=r"((r)[1]), "=r"((r)[2]), "=r"((r)[3])    \
                 : "r"(addr))
#define LDMT4(r, addr)                                                       \
    asm volatile("ldmatrix.sync.aligned.m8n8.x4.trans.shared.b16 {%0,%1,%2,%3}, [%4];" \
                 : "=r"((r)[0]), "=r"((r)[1]), "=r"((r)[2]), "=r"((r)[3])    \
                 : "r"(addr))
#define MMA(d, a, b0, b1)                                                    \
    asm volatile(                                                            \
        "mma.sync.aligned.m16n8k16.row.col.f32.bf16.bf16.f32 "               \
        "{%0,%1,%2,%3}, {%4,%5,%6,%7}, {%8,%9}, {%0,%1,%2,%3};"              \
        : "+f"((d)[0]), "+f"((d)[1]), "+f"((d)[2]), "+f"((d)[3])             \
        : "r"((a)[0]), "r"((a)[1]), "r"((a)[2]), "r"((a)[3]),                \
          "r"(b0), "r"(b1))
#define CP16(dst, src)                                                       \
    asm volatile("cp.async.cg.shared.global [%0], [%1], 16;"                 \
                 :: "r"(dst), "l"(src))
#define CP_COMMIT() asm volatile("cp.async.commit_group;")
#define CP_WAIT1()  asm volatile("cp.async.wait_group 1;")
#define CP_WAIT0()  asm volatile("cp.async.wait_group 0;")

// ---------------- weight split (k-major), 2 elems/thread ----------------------
__global__ __launch_bounds__(256) void prep_w(
    const float* __restrict__ Wq, const float* __restrict__ Wk,
    const float* __restrict__ Wv)
{
    int q = blockIdx.x * 256 + threadIdx.x;      // over EMB*CCOLS/2 = 73728
    if (q >= EMB * CCOLS / 2) return;
    int n2 = (q % (CCOLS / 2)) * 2;
    int k  = q / (CCOLS / 2);
    const float* W = (n2 < 64) ? Wq : (n2 < 128) ? Wk : Wv;
    const float* src = W + (size_t)k * 64 + (n2 & 63);
    float2 v = *(const float2*)src;
    __nv_bfloat162 h01 = __floats2bfloat162_rn(v.x, v.y);
    float l0 = v.x - __bfloat162float(h01.x);
    float l1 = v.y - __bfloat162float(h01.y);
    __nv_bfloat162 p01 = __floats2bfloat162_rn(l0, l1);
    size_t o = (size_t)k * CCOLS + n2;
    *(uint32_t*)(g_Bh + o) = *(uint32_t*)&h01;
    *(uint32_t*)(g_Bl + o) = *(uint32_t*)&p01;
}

// ---------------- pipelined bf16-split HMMA GEMM (R11/R13 config) --------------
#define SA_BYTES (128 * 144)
#define SB_BYTES (64 * 400)
#define SA_OFF(s, h) (((s) * 2 + (h)) * SA_BYTES)
#define SB_OFF(s, h) (4 * SA_BYTES + ((s) * 2 + (h)) * SB_BYTES)
#define SM_TOTAL (4 * SA_BYTES + 4 * SB_BYTES)   // 176128

__global__ __launch_bounds__(256, 1)
void mma_gemm(const float* __restrict__ x,
              const float* __restrict__ bq, const float* __restrict__ bk,
              const float* __restrict__ bv)
{
    extern __shared__ char smem[];
    __shared__ float sbias[CCOLS];
    __shared__ float smemV[4][64];

    const uint32_t sb = smem_u32(smem);
    const int tid = threadIdx.x;
    const int wid = tid >> 5, lane = tid & 31;
    const int wm = wid & 3, wn = wid >> 2;
    const int rowTile = blockIdx.x * 128;

    if (tid < CCOLS)
        sbias[tid] = (tid < 64) ? bq[tid] : (tid < 128) ? bk[tid - 64]
                                                        : bv[tid - 128];

    float acc[2][12][4];
#pragma unroll
    for (int i = 0; i < 2; i++)
#pragma unroll
        for (int j = 0; j < 12; j++)
#pragma unroll
            for (int l = 0; l < 4; l++) acc[i][j][l] = 0.f;

    const int g = lane >> 3, r = lane & 7;
    const int a_off = (r + ((g & 1) ? 8 : 0)) * 144 + (((g >= 2) ? 8 : 0) * 2);
    const int b_off = ((g & 1) * 8 + r) * 400 + (((g >= 2) ? 8 : 0) * 2);

    uint32_t aAh[2], aAl[2], aBh[2], aBl[2];
#pragma unroll
    for (int s = 0; s < 2; s++) {
        aAh[s] = sb + SA_OFF(s, 0) + wm * 32 * 144 + a_off;
        aAl[s] = sb + SA_OFF(s, 1) + wm * 32 * 144 + a_off;
        aBh[s] = sb + SB_OFF(s, 0) + wn * 96 * 2 + b_off;
        aBl[s] = sb + SB_OFF(s, 1) + wn * 96 * 2 + b_off;
    }

    // raw A fp32 in registers, one chunk ahead; converted at STS time
    float4 Av[8];

#define LDG_A_RAW(ch)                                                        \
    do {                                                                     \
        const int k0_ = (ch) * 64;                                           \
        _Pragma("unroll")                                                    \
        for (int i = 0; i < 8; i++) {                                        \
            int idx = tid + i * 256;                                         \
            int rr = idx >> 4, c4 = idx & 15;                                \
            Av[i] = *(const float4*)(x + (size_t)(rowTile + rr) * EMB +      \
                                     k0_ + c4 * 4);                          \
        }                                                                    \
    } while (0)

#define STS_A_CONV(ch)                                                       \
    do {                                                                     \
        const int s_ = (ch) & 1;                                             \
        _Pragma("unroll")                                                    \
        for (int i = 0; i < 8; i++) {                                        \
            int idx = tid + i * 256;                                         \
            int rr = idx >> 4, c4 = idx & 15;                                \
            float4 v = Av[i];                                                \
            __nv_bfloat162 h01 = __floats2bfloat162_rn(v.x, v.y);            \
            __nv_bfloat162 h23 = __floats2bfloat162_rn(v.z, v.w);            \
            float l0 = v.x - __bfloat162float(h01.x);                        \
            float l1 = v.y - __bfloat162float(h01.y);                        \
            float l2 = v.z - __bfloat162float(h23.x);                        \
            float l3 = v.w - __bfloat162float(h23.y);                        \
            __nv_bfloat162 p01 = __floats2bfloat162_rn(l0, l1);              \
            __nv_bfloat162 p23 = __floats2bfloat162_rn(l2, l3);              \
            *(uint2*)(smem + SA_OFF(s_, 0) + rr * 144 + c4 * 8) =            \
                make_uint2(*(uint32_t*)&h01, *(uint32_t*)&h23);              \
            *(uint2*)(smem + SA_OFF(s_, 1) + rr * 144 + c4 * 8) =            \
                make_uint2(*(uint32_t*)&p01, *(uint32_t*)&p23);              \
        }                                                                    \
    } while (0)

#define LDG_B(ch)                                                            \
    do {                                                                     \
        const int s_ = (ch) & 1;                                             \
        const int k0_ = (ch) * 64;                                           \
        _Pragma("unroll")                                                    \
        for (int i = 0; i < 6; i++) {                                        \
            int j = tid + i * 256;                                           \
            int row = j / 24, c = j % 24;                                    \
            uint32_t dh = sb + SB_OFF(s_, 0) + row * 400 + c * 16;           \
            uint32_t dl = sb + SB_OFF(s_, 1) + row * 400 + c * 16;           \
            CP16(dh, g_Bh + (size_t)(k0_ + row) * CCOLS + c * 8);            \
            CP16(dl, g_Bl + (size_t)(k0_ + row) * CCOLS + c * 8);            \
        }                                                                    \
    } while (0)

    // ---- prologue ----
    LDG_B(0); CP_COMMIT();
    LDG_A_RAW(0);
    STS_A_CONV(0);
    LDG_B(1); CP_COMMIT();
    LDG_A_RAW(1);

    // ---- main loop ----
    for (int ch = 0; ch < 12; ch++) {
        const int s = ch & 1;
        if (ch < 11) CP_WAIT1(); else CP_WAIT0();
        __syncthreads();

#pragma unroll
        for (int ks = 0; ks < 4; ks++) {
            uint32_t ah[2][4], al[2][4];
            LDM4(ah[0], aAh[s] + ks * 32);
            LDM4(ah[1], aAh[s] + 16 * 144 + ks * 32);
            LDM4(al[0], aAl[s] + ks * 32);
            LDM4(al[1], aAl[s] + 16 * 144 + ks * 32);

            uint32_t bh[2][4], bl[2][4];
            LDMT4(bh[0], aBh[s] + ks * 6400);
            LDMT4(bl[0], aBl[s] + ks * 6400);
#pragma unroll
            for (int nt = 0; nt < 6; nt++) {
                const int cur = nt & 1, nxt = cur ^ 1;
                if (nt < 5) {
                    LDMT4(bh[nxt], aBh[s] + ks * 6400 + (nt + 1) * 32);
                    LDMT4(bl[nxt], aBl[s] + ks * 6400 + (nt + 1) * 32);
                }
#pragma unroll
                for (int mt = 0; mt < 2; mt++) {
                    MMA(acc[mt][2 * nt],     ah[mt], bh[cur][0], bh[cur][1]);
                    MMA(acc[mt][2 * nt],     ah[mt], bl[cur][0], bl[cur][1]);
                    MMA(acc[mt][2 * nt],     al[mt], bh[cur][0], bh[cur][1]);
                    MMA(acc[mt][2 * nt + 1], ah[mt], bh[cur][2], bh[cur][3]);
                    MMA(acc[mt][2 * nt + 1], ah[mt], bl[cur][2], bl[cur][3]);
                    MMA(acc[mt][2 * nt + 1], al[mt], bh[cur][2], bh[cur][3]);
                }
            }
            if (ks == 0 && ch < 11)
                STS_A_CONV(ch + 1);   // A[s^1] only — safe
        }
        if (ch < 10) {
            __syncthreads();          // all reads of B[s] complete
            LDG_B(ch + 2); CP_COMMIT();
            LDG_A_RAW(ch + 2);
        }
    }

    // ---- epilogue: acc + bias -> g_C ----
    const int rbase = rowTile + wm * 32 + (lane >> 2);
#pragma unroll
    for (int mt = 0; mt < 2; mt++)
#pragma unroll
        for (int nt = 0; nt < 12; nt++) {
            int col = wn * 96 + nt * 8 + 2 * (lane & 3);
            float b0 = sbias[col], b1 = sbias[col + 1];
            int row = rbase + mt * 16;
            *(float2*)&g_C[(size_t)row * CCOLS + col] =
                make_float2(acc[mt][nt][0] + b0, acc[mt][nt][1] + b1);
            *(float2*)&g_C[(size_t)(row + 8) * CCOLS + col] =
                make_float2(acc[mt][nt][2] + b0, acc[mt][nt][3] + b1);
        }

    // ---- per-CTA V column sums ----
    if (wn == 1) {
#pragma unroll
        for (int nt = 4; nt < 12; nt++) {
            float s0 = acc[0][nt][0] + acc[0][nt][2] + acc[1][nt][0] + acc[1][nt][2];
            float s1 = acc[0][nt][1] + acc[0][nt][3] + acc[1][nt][1] + acc[1][nt][3];
#pragma unroll
            for (int m = 4; m <= 16; m <<= 1) {
                s0 += __shfl_xor_sync(0xffffffffu, s0, m);
                s1 += __shfl_xor_sync(0xffffffffu, s1, m);
            }
            if (lane < 4) {
                int d = (nt - 4) * 8 + 2 * lane;
                smemV[wm][d] = s0;
                smemV[wm][d + 1] = s1;
            }
        }
    }
    __syncthreads();
    if (tid < 64)
        g_Spart[blockIdx.x * 64 + tid] =
            smemV[0][tid] + smemV[1][tid] + smemV[2][tid] + smemV[3][tid] +
            128.f * sbias[128 + tid];
}

// ---------------- parallel final V-sum: 4 blocks, two-stage --------------------
__global__ __launch_bounds__(256) void sum_v_final()
{
    __shared__ float sm[4][64];
    const int b = blockIdx.x;
    const int d = threadIdx.x & 63;
    const int grp = threadIdx.x >> 6;
    float s = 0.f;
#pragma unroll
    for (int c = 0; c < 8; c++)
        s += g_Spart[(b * 32 + grp * 8 + c) * 64 + d];
    sm[grp][d] = s;
    __syncthreads();
    if (grp == 0) {
        float t = sm[0][d] + sm[1][d] + sm[2][d] + sm[3][d];
#pragma unroll
        for (int j = 0; j < 3; j++)
            t -= g_C[(size_t)(b * SEQ + j) * CCOLS + 128 + d];
        g_S[b * 64 + d] = t;
    }
}

// ---------------- epilogue: TWO rows per warp (shared K loads) -----------------
__global__ __launch_bounds__(256) void attn_epilogue(float* __restrict__ out)
{
    const int lane = threadIdx.x;
    const int r0 = (blockIdx.x * 8 + threadIdx.y) * 2;   // even row
    const int r1 = r0 + 1;
    const int loc0 = r0 & (SEQ - 1);
    const int loc1 = r1 & (SEQ - 1);
    const int b = r0 >> 12;

    const float* C0 = g_C + (size_t)r0 * CCOLS;
    float2 q0 = *(const float2*)(C0 + lane * 2);
    float2 q1 = *(const float2*)(C0 + CCOLS + lane * 2);

    const float* K0 = C0 + 64;                 // K(r0)
    float2 k0  = *(const float2*)(K0 + lane * 2);
    float2 k1  = *(const float2*)(K0 + CCOLS + lane * 2);       // K(r1)
    float2 km1 = make_float2(0.f, 0.f), k2 = make_float2(0.f, 0.f);
    if (loc0 > 0)
        km1 = *(const float2*)(K0 - CCOLS + lane * 2);
    if (loc1 < SEQ - 1)
        k2 = *(const float2*)(K0 + 2 * CCOLS + lane * 2);

    // six partial dots
    float dA = q0.x * km1.x + q0.y * km1.y;    // d0 of r0
    float dB = q0.x * k0.x + q0.y * k0.y;      // d1 of r0
    float dC = q0.x * k1.x + q0.y * k1.y;      // d2 of r0
    float dD = q1.x * k0.x + q1.y * k0.y;      // d0 of r1
    float dE = q1.x * k1.x + q1.y * k1.y;      // d1 of r1
    float dF = q1.x * k2.x + q1.y * k2.y;      // d2 of r1
#pragma unroll
    for (int off = 16; off; off >>= 1) {
        dA += __shfl_xor_sync(0xffffffffu, dA, off);
        dB += __shfl_xor_sync(0xffffffffu, dB, off);
        dC += __shfl_xor_sync(0xffffffffu, dC, off);
        dD += __shfl_xor_sync(0xffffffffu, dD, off);
        dE += __shfl_xor_sync(0xffffffffu, dE, off);
        dF += __shfl_xor_sync(0xffffffffu, dF, off);
    }
    float e0_0 = (loc0 > 0) ? __expf(dA) : 1.f;
    float e1_0 = __expf(dB);
    float e2_0 = __expf(dC);                   // loc0 even -> never SEQ-1
    float e0_1 = __expf(dD);                   // loc1 odd  -> never 0
    float e1_1 = __expf(dE);
    float e2_1 = (loc1 < SEQ - 1) ? __expf(dF) : 1.f;
    float rZ0 = __fdividef(1.f, e0_0 + e1_0 + e2_0 + (float)(SEQ - 3));
    float rZ1 = __fdividef(1.f, e0_1 + e1_1 + e2_1 + (float)(SEQ - 3));

    const float* Vb = g_C + (size_t)(b * SEQ) * CCOLS + 128;
    float2 v0 = *(const float2*)(Vb + lane * 2);
    float2 v1 = *(const float2*)(Vb + CCOLS + lane * 2);
    float2 v2 = *(const float2*)(Vb + 2 * CCOLS + lane * 2);
    float2 s  = *(const float2*)(g_S + b * 64 + lane * 2);

    float2 o0, o1;
    o0.x = (e0_0 * v0.x + e1_0 * v1.x + e2_0 * v2.x + s.x) * rZ0;
    o0.y = (e0_0 * v0.y + e1_0 * v1.y + e2_0 * v2.y + s.y) * rZ0;
    o1.x = (e0_1 * v0.x + e1_1 * v1.x + e2_1 * v2.x + s.x) * rZ1;
    o1.y = (e0_1 * v0.y + e1_1 * v1.y + e2_1 * v2.y + s.y) * rZ1;
    *(float2*)(out + (size_t)r0 * QD + lane * 2) = o0;
    *(float2*)(out + (size_t)r1 * QD + lane * 2) = o1;
}

// ---------------- launch -------------------------------------------------------
extern "C" void kernel_launch(void* const* d_in, const int* in_sizes, int n_in,
                              void* d_out, int out_size)
{
    const float* x  = (const float*)d_in[0];
    const float* Wq = (const float*)d_in[1];
    const float* bq = (const float*)d_in[2];
    const float* Wk = (const float*)d_in[3];
    const float* bk = (const float*)d_in[4];
    const float* Wv = (const float*)d_in[5];
    const float* bv = (const float*)d_in[6];
    float* out = (float*)d_out;

    cudaFuncSetAttribute(mma_gemm, cudaFuncAttributeMaxDynamicSharedMemorySize,
                         SM_TOTAL);

    prep_w<<<(EMB * CCOLS / 2 + 255) / 256, 256>>>(Wq, Wk, Wv);
    mma_gemm<<<NROWS / 128, 256, SM_TOTAL>>>(x, bq, bk, bv);
    sum_v_final<<<BATCH, 256>>>();
    attn_epilogue<<<NROWS / 16, dim3(32, 8)>>>(out);
}

// round 16
// speedup vs baseline: 2.4408x; 1.0039x over previous
#include <cuda_runtime.h>
#include <cuda_bf16.h>
#include <math.h>
#include <stdint.h>

#define BATCH 4
#define SEQ   4096
#define NROWS (BATCH * SEQ)
#define EMB   768
#define QD    64
#define CCOLS 192
#define NCTAS 128

// ---------------- scratch ----------------------------------------------------
__device__ float g_C[(size_t)NROWS * CCOLS];
__device__ __nv_bfloat16 g_Bh[(size_t)EMB * CCOLS];  // k-major: [k][n]
__device__ __nv_bfloat16 g_Bl[(size_t)EMB * CCOLS];
__device__ float g_Spart[128 * 64];                  // per-CTA V col sums
__device__ float g_S[BATCH * QD];
__device__ unsigned g_barCnt = 0;                    // monotonic, replay-safe

// ---------------- PTX helpers ------------------------------------------------
__device__ __forceinline__ uint32_t smem_u32(const void* p) {
    uint32_t a;
    asm("{ .reg .u64 t; cvta.to.shared.u64 t, %1; cvt.u32.u64 %0, t; }"
        : "=r"(a) : "l"(p));
    return a;
}
#define LDM4(r, addr)                                                        \
    asm volatile("ldmatrix.sync.aligned.m8n8.x4.shared.b16 {%0,%1,%2,%3}, [%4];" \
                 : "=r"((r)[0]), "=r"((r)[1]), "=r"((r)[2]), "=r"((r)[3])    \
                 : "r"(addr))
#define LDMT4(r, addr)                                                       \
    asm volatile("ldmatrix.sync.aligned.m8n8.x4.trans.shared.b16 {%0,%1,%2,%3}, [%4];" \
                 : "=r"((r)[0]), "=r"((r)[1]), "=r"((r)[2]), "=r"((r)[3])    \
                 : "r"(addr))
#define MMA(d, a, b0, b1)                                                    \
    asm volatile(                                                            \
        "mma.sync.aligned.m16n8k16.row.col.f32.bf16.bf16.f32 "               \
        "{%0,%1,%2,%3}, {%4,%5,%6,%7}, {%8,%9}, {%0,%1,%2,%3};"              \
        : "+f"((d)[0]), "+f"((d)[1]), "+f"((d)[2]), "+f"((d)[3])             \
        : "r"((a)[0]), "r"((a)[1]), "r"((a)[2]), "r"((a)[3]),                \
          "r"(b0), "r"(b1))
#define CP16(dst, src)                                                       \
    asm volatile("cp.async.cg.shared.global [%0], [%1], 16;"                 \
                 :: "r"(dst), "l"(src))
#define CP_COMMIT() asm volatile("cp.async.commit_group;")
#define CP_WAIT1()  asm volatile("cp.async.wait_group 1;")
#define CP_WAIT0()  asm volatile("cp.async.wait_group 0;")

// Grid-wide barrier. Safe: all 128 CTAs resident (1 CTA/SM via 176KB smem,
// 128 < 148 SMs -> single wave). Monotonic counter, no reset, replay-safe.
__device__ __forceinline__ void grid_barrier() {
    __syncthreads();
    if (threadIdx.x == 0) {
        __threadfence();
        unsigned my = atomicAdd(&g_barCnt, 1u);
        unsigned target = (my & ~(unsigned)(NCTAS - 1)) + NCTAS;
        while ((int)(*(volatile unsigned*)&g_barCnt - target) < 0)
            __nanosleep(64);
        __threadfence();
    }
    __syncthreads();
}

// ---------------- pipelined bf16-split HMMA GEMM + fused weight prep ----------
#define SA_BYTES (128 * 144)
#define SB_BYTES (64 * 400)
#define SA_OFF(s, h) (((s) * 2 + (h)) * SA_BYTES)
#define SB_OFF(s, h) (4 * SA_BYTES + ((s) * 2 + (h)) * SB_BYTES)
#define SM_TOTAL (4 * SA_BYTES + 4 * SB_BYTES)   // 176128

__global__ __launch_bounds__(256, 1)
void mma_gemm(const float* __restrict__ x,
              const float* __restrict__ Wq, const float* __restrict__ bq,
              const float* __restrict__ Wk, const float* __restrict__ bk,
              const float* __restrict__ Wv, const float* __restrict__ bv)
{
    extern __shared__ char smem[];
    __shared__ float sbias[CCOLS];
    __shared__ float smemV[4][64];

    const uint32_t sb = smem_u32(smem);
    const int tid = threadIdx.x;
    const int wid = tid >> 5, lane = tid & 31;
    const int wm = wid & 3, wn = wid >> 2;
    const int rowTile = blockIdx.x * 128;

    // ---- phase 0: weight split, my 1/128 slice (576 float2 pairs) ----
    {
        const int base = blockIdx.x * (EMB * CCOLS / 2 / NCTAS);
        for (int t = tid; t < EMB * CCOLS / 2 / NCTAS; t += 256) {
            int q = base + t;
            int n2 = (q % (CCOLS / 2)) * 2;
            int k  = q / (CCOLS / 2);
            const float* W = (n2 < 64) ? Wq : (n2 < 128) ? Wk : Wv;
            float2 v = *(const float2*)(W + (size_t)k * 64 + (n2 & 63));
            __nv_bfloat162 h01 = __floats2bfloat162_rn(v.x, v.y);
            float l0 = v.x - __bfloat162float(h01.x);
            float l1 = v.y - __bfloat162float(h01.y);
            __nv_bfloat162 p01 = __floats2bfloat162_rn(l0, l1);
            size_t o = (size_t)k * CCOLS + n2;
            *(uint32_t*)(g_Bh + o) = *(uint32_t*)&h01;
            *(uint32_t*)(g_Bl + o) = *(uint32_t*)&p01;
        }
    }
    if (tid < CCOLS)
        sbias[tid] = (tid < 64) ? bq[tid] : (tid < 128) ? bk[tid - 64]
                                                        : bv[tid - 128];
    grid_barrier();

    // ---- phase 1: GEMM (byte-identical to R13) ----
    float acc[2][12][4];
#pragma unroll
    for (int i = 0; i < 2; i++)
#pragma unroll
        for (int j = 0; j < 12; j++)
#pragma unroll
            for (int l = 0; l < 4; l++) acc[i][j][l] = 0.f;

    const int g = lane >> 3, r = lane & 7;
    const int a_off = (r + ((g & 1) ? 8 : 0)) * 144 + (((g >= 2) ? 8 : 0) * 2);
    const int b_off = ((g & 1) * 8 + r) * 400 + (((g >= 2) ? 8 : 0) * 2);

    uint32_t aAh[2], aAl[2], aBh[2], aBl[2];
#pragma unroll
    for (int s = 0; s < 2; s++) {
        aAh[s] = sb + SA_OFF(s, 0) + wm * 32 * 144 + a_off;
        aAl[s] = sb + SA_OFF(s, 1) + wm * 32 * 144 + a_off;
        aBh[s] = sb + SB_OFF(s, 0) + wn * 96 * 2 + b_off;
        aBl[s] = sb + SB_OFF(s, 1) + wn * 96 * 2 + b_off;
    }

    float4 Av[8];

#define LDG_A_RAW(ch)                                                        \
    do {                                                                     \
        const int k0_ = (ch) * 64;                                           \
        _Pragma("unroll")                                                    \
        for (int i = 0; i < 8; i++) {                                        \
            int idx = tid + i * 256;                                         \
            int rr = idx >> 4, c4 = idx & 15;                                \
            Av[i] = *(const float4*)(x + (size_t)(rowTile + rr) * EMB +      \
                                     k0_ + c4 * 4);                          \
        }                                                                    \
    } while (0)

#define STS_A_CONV(ch)                                                       \
    do {                                                                     \
        const int s_ = (ch) & 1;                                             \
        _Pragma("unroll")                                                    \
        for (int i = 0; i < 8; i++) {                                        \
            int idx = tid + i * 256;                                         \
            int rr = idx >> 4, c4 = idx & 15;                                \
            float4 v = Av[i];                                                \
            __nv_bfloat162 h01 = __floats2bfloat162_rn(v.x, v.y);            \
            __nv_bfloat162 h23 = __floats2bfloat162_rn(v.z, v.w);            \
            float l0 = v.x - __bfloat162float(h01.x);                        \
            float l1 = v.y - __bfloat162float(h01.y);                        \
            float l2 = v.z - __bfloat162float(h23.x);                        \
            float l3 = v.w - __bfloat162float(h23.y);                        \
            __nv_bfloat162 p01 = __floats2bfloat162_rn(l0, l1);              \
            __nv_bfloat162 p23 = __floats2bfloat162_rn(l2, l3);              \
            *(uint2*)(smem + SA_OFF(s_, 0) + rr * 144 + c4 * 8) =            \
                make_uint2(*(uint32_t*)&h01, *(uint32_t*)&h23);              \
            *(uint2*)(smem + SA_OFF(s_, 1) + rr * 144 + c4 * 8) =            \
                make_uint2(*(uint32_t*)&p01, *(uint32_t*)&p23);              \
        }                                                                    \
    } while (0)

#define LDG_B(ch)                                                            \
    do {                                                                     \
        const int s_ = (ch) & 1;                                             \
        const int k0_ = (ch) * 64;                                           \
        _Pragma("unroll")                                                    \
        for (int i = 0; i < 6; i++) {                                        \
            int j = tid + i * 256;                                           \
            int row = j / 24, c = j % 24;                                    \
            uint32_t dh = sb + SB_OFF(s_, 0) + row * 400 + c * 16;           \
            uint32_t dl = sb + SB_OFF(s_, 1) + row * 400 + c * 16;           \
            CP16(dh, g_Bh + (size_t)(k0_ + row) * CCOLS + c * 8);            \
            CP16(dl, g_Bl + (size_t)(k0_ + row) * CCOLS + c * 8);            \
        }                                                                    \
    } while (0)

    // ---- prologue ----
    LDG_B(0); CP_COMMIT();
    LDG_A_RAW(0);
    STS_A_CONV(0);
    LDG_B(1); CP_COMMIT();
    LDG_A_RAW(1);

    // ---- main loop ----
    for (int ch = 0; ch < 12; ch++) {
        const int s = ch & 1;
        if (ch < 11) CP_WAIT1(); else CP_WAIT0();
        __syncthreads();

#pragma unroll
        for (int ks = 0; ks < 4; ks++) {
            uint32_t ah[2][4], al[2][4];
            LDM4(ah[0], aAh[s] + ks * 32);
            LDM4(ah[1], aAh[s] + 16 * 144 + ks * 32);
            LDM4(al[0], aAl[s] + ks * 32);
            LDM4(al[1], aAl[s] + 16 * 144 + ks * 32);

            uint32_t bh[2][4], bl[2][4];
            LDMT4(bh[0], aBh[s] + ks * 6400);
            LDMT4(bl[0], aBl[s] + ks * 6400);
#pragma unroll
            for (int nt = 0; nt < 6; nt++) {
                const int cur = nt & 1, nxt = cur ^ 1;
                if (nt < 5) {
                    LDMT4(bh[nxt], aBh[s] + ks * 6400 + (nt + 1) * 32);
                    LDMT4(bl[nxt], aBl[s] + ks * 6400 + (nt + 1) * 32);
                }
#pragma unroll
                for (int mt = 0; mt < 2; mt++) {
                    MMA(acc[mt][2 * nt],     ah[mt], bh[cur][0], bh[cur][1]);
                    MMA(acc[mt][2 * nt],     ah[mt], bl[cur][0], bl[cur][1]);
                    MMA(acc[mt][2 * nt],     al[mt], bh[cur][0], bh[cur][1]);
                    MMA(acc[mt][2 * nt + 1], ah[mt], bh[cur][2], bh[cur][3]);
                    MMA(acc[mt][2 * nt + 1], ah[mt], bl[cur][2], bl[cur][3]);
                    MMA(acc[mt][2 * nt + 1], al[mt], bh[cur][2], bh[cur][3]);
                }
            }
            if (ks == 0 && ch < 11)
                STS_A_CONV(ch + 1);   // A[s^1] only — safe
        }
        if (ch < 10) {
            __syncthreads();          // all reads of B[s] complete
            LDG_B(ch + 2); CP_COMMIT();
            LDG_A_RAW(ch + 2);
        }
    }

    // ---- epilogue: acc + bias -> g_C ----
    const int rbase = rowTile + wm * 32 + (lane >> 2);
#pragma unroll
    for (int mt = 0; mt < 2; mt++)
#pragma unroll
        for (int nt = 0; nt < 12; nt++) {
            int col = wn * 96 + nt * 8 + 2 * (lane & 3);
            float b0 = sbias[col], b1 = sbias[col + 1];
            int row = rbase + mt * 16;
            *(float2*)&g_C[(size_t)row * CCOLS + col] =
                make_float2(acc[mt][nt][0] + b0, acc[mt][nt][1] + b1);
            *(float2*)&g_C[(size_t)(row + 8) * CCOLS + col] =
                make_float2(acc[mt][nt][2] + b0, acc[mt][nt][3] + b1);
        }

    // ---- per-CTA V column sums ----
    if (wn == 1) {
#pragma unroll
        for (int nt = 4; nt < 12; nt++) {
            float s0 = acc[0][nt][0] + acc[0][nt][2] + acc[1][nt][0] + acc[1][nt][2];
            float s1 = acc[0][nt][1] + acc[0][nt][3] + acc[1][nt][1] + acc[1][nt][3];
#pragma unroll
            for (int m = 4; m <= 16; m <<= 1) {
                s0 += __shfl_xor_sync(0xffffffffu, s0, m);
                s1 += __shfl_xor_sync(0xffffffffu, s1, m);
            }
            if (lane < 4) {
                int d = (nt - 4) * 8 + 2 * lane;
                smemV[wm][d] = s0;
                smemV[wm][d + 1] = s1;
            }
        }
    }
    __syncthreads();
    if (tid < 64)
        g_Spart[blockIdx.x * 64 + tid] =
            smemV[0][tid] + smemV[1][tid] + smemV[2][tid] + smemV[3][tid] +
            128.f * sbias[128 + tid];
}

// ---------------- parallel final V-sum: 4 blocks, two-stage --------------------
__global__ __launch_bounds__(256) void sum_v_final()
{
    __shared__ float sm[4][64];
    const int b = blockIdx.x;
    const int d = threadIdx.x & 63;
    const int grp = threadIdx.x >> 6;
    float s = 0.f;
#pragma unroll
    for (int c = 0; c < 8; c++)
        s += g_Spart[(b * 32 + grp * 8 + c) * 64 + d];
    sm[grp][d] = s;
    __syncthreads();
    if (grp == 0) {
        float t = sm[0][d] + sm[1][d] + sm[2][d] + sm[3][d];
#pragma unroll
        for (int j = 0; j < 3; j++)
            t -= g_C[(size_t)(b * SEQ + j) * CCOLS + 128 + d];
        g_S[b * 64 + d] = t;
    }
}

// ---------------- epilogue: TWO rows per warp (shared K loads) -----------------
__global__ __launch_bounds__(256) void attn_epilogue(float* __restrict__ out)
{
    const int lane = threadIdx.x;
    const int r0 = (blockIdx.x * 8 + threadIdx.y) * 2;
    const int r1 = r0 + 1;
    const int loc0 = r0 & (SEQ - 1);
    const int loc1 = r1 & (SEQ - 1);
    const int b = r0 >> 12;

    const float* C0 = g_C + (size_t)r0 * CCOLS;
    float2 q0 = *(const float2*)(C0 + lane * 2);
    float2 q1 = *(const float2*)(C0 + CCOLS + lane * 2);

    const float* K0 = C0 + 64;
    float2 k0  = *(const float2*)(K0 + lane * 2);
    float2 k1  = *(const float2*)(K0 + CCOLS + lane * 2);
    float2 km1 = make_float2(0.f, 0.f), k2 = make_float2(0.f, 0.f);
    if (loc0 > 0)
        km1 = *(const float2*)(K0 - CCOLS + lane * 2);
    if (loc1 < SEQ - 1)
        k2 = *(const float2*)(K0 + 2 * CCOLS + lane * 2);

    float dA = q0.x * km1.x + q0.y * km1.y;
    float dB = q0.x * k0.x + q0.y * k0.y;
    float dC = q0.x * k1.x + q0.y * k1.y;
    float dD = q1.x * k0.x + q1.y * k0.y;
    float dE = q1.x * k1.x + q1.y * k1.y;
    float dF = q1.x * k2.x + q1.y * k2.y;
#pragma unroll
    for (int off = 16; off; off >>= 1) {
        dA += __shfl_xor_sync(0xffffffffu, dA, off);
        dB += __shfl_xor_sync(0xffffffffu, dB, off);
        dC += __shfl_xor_sync(0xffffffffu, dC, off);
        dD += __shfl_xor_sync(0xffffffffu, dD, off);
        dE += __shfl_xor_sync(0xffffffffu, dE, off);
        dF += __shfl_xor_sync(0xffffffffu, dF, off);
    }
    float e0_0 = (loc0 > 0) ? __expf(dA) : 1.f;
    float e1_0 = __expf(dB);
    float e2_0 = __expf(dC);
    float e0_1 = __expf(dD);
    float e1_1 = __expf(dE);
    float e2_1 = (loc1 < SEQ - 1) ? __expf(dF) : 1.f;
    float rZ0 = __fdividef(1.f, e0_0 + e1_0 + e2_0 + (float)(SEQ - 3));
    float rZ1 = __fdividef(1.f, e0_1 + e1_1 + e2_1 + (float)(SEQ - 3));

    const float* Vb = g_C + (size_t)(b * SEQ) * CCOLS + 128;
    float2 v0 = *(const float2*)(Vb + lane * 2);
    float2 v1 = *(const float2*)(Vb + CCOLS + lane * 2);
    float2 v2 = *(const float2*)(Vb + 2 * CCOLS + lane * 2);
    float2 s  = *(const float2*)(g_S + b * 64 + lane * 2);

    float2 o0, o1;
    o0.x = (e0_0 * v0.x + e1_0 * v1.x + e2_0 * v2.x + s.x) * rZ0;
    o0.y = (e0_0 * v0.y + e1_0 * v1.y + e2_0 * v2.y + s.y) * rZ0;
    o1.x = (e0_1 * v0.x + e1_1 * v1.x + e2_1 * v2.x + s.x) * rZ1;
    o1.y = (e0_1 * v0.y + e1_1 * v1.y + e2_1 * v2.y + s.y) * rZ1;
    *(float2*)(out + (size_t)r0 * QD + lane * 2) = o0;
    *(float2*)(out + (size_t)r1 * QD + lane * 2) = o1;
}

// ---------------- launch -------------------------------------------------------
extern "C" void kernel_launch(void* const* d_in, const int* in_sizes, int n_in,
                              void* d_out, int out_size)
{
    const float* x  = (const float*)d_in[0];
    const float* Wq = (const float*)d_in[1];
    const float* bq = (const float*)d_in[2];
    const float* Wk = (const float*)d_in[3];
    const float* bk = (const float*)d_in[4];
    const float* Wv = (const float*)d_in[5];
    const float* bv = (const float*)d_in[6];
    float* out = (float*)d_out;

    cudaFuncSetAttribute(mma_gemm, cudaFuncAttributeMaxDynamicSharedMemorySize,
                         SM_TOTAL);

    mma_gemm<<<NCTAS, 256, SM_TOTAL>>>(x, Wq, bq, Wk, bk, Wv, bv);
    sum_v_final<<<BATCH, 256>>>();
    attn_epilogue<<<NROWS / 16, dim3(32, 8)>>>(out);
}